// round 1
// baseline (speedup 1.0000x reference)
#include <cuda_runtime.h>
#include <cuda_bf16.h>
#include <math.h>

// Problem constants
#define BB   32
#define HH   14
#define WW   14
#define CC   32
#define KK   64
#define KS   5
#define OH   10
#define OW   10
#define PP   100      // OH*OW
#define NPOS 196      // H*W
#define MM   800      // KS*KS*C
#define IMG  6272     // NPOS*CC floats per batch

// Scratch (device globals; no allocation allowed)
__device__ float  g_ds[BB * IMG];          // diag(Sigma_in) image, [b][pos][c]
__device__ float2 g_wp[(MM/2) * KK];       // paired weights: {w[2m2][k], w[2m2+1][k]} at [m2*64+k]
__device__ float  g_sp[KK];                // softplus(w_sigma)
__device__ float  g_dv[BB * PP * KK];      // diag_vals
__device__ float  g_G[BB * PP * PP];       // Gram matrices

// ---------------- f32x2 packed helpers ----------------
typedef unsigned long long ull;

__device__ __forceinline__ ull f2fma(ull a, ull b, ull c) {
    ull d;
    asm("fma.rn.f32x2 %0, %1, %2, %3;" : "=l"(d) : "l"(a), "l"(b), "l"(c));
    return d;
}
__device__ __forceinline__ ull f2mul(ull a, ull b) {
    ull d;
    asm("mul.rn.f32x2 %0, %1, %2;" : "=l"(d) : "l"(a), "l"(b));
    return d;
}
__device__ __forceinline__ float f2sum(ull v) {
    float lo, hi;
    asm("mov.b64 {%0, %1}, %2;" : "=f"(lo), "=f"(hi) : "l"(v));
    return lo + hi;
}

// ---------------- Kernel 1: prep ----------------
// 1) gather diagonal of Sigma_in -> g_ds
// 2) pair-transpose w_mu -> g_wp
// 3) softplus(w_sigma) -> g_sp
__global__ __launch_bounds__(256) void k_prep(const float* __restrict__ Sg,
                                              const float* __restrict__ w_mu,
                                              const float* __restrict__ w_sigma) {
    int idx = blockIdx.x * 256 + threadIdx.x;
    if (idx < BB * IMG) {
        int b   = idx / IMG;
        int r   = idx - b * IMG;
        int pos = r >> 5;
        int c   = r & 31;
        // Sigma_in[b, pos, pos, c]
        g_ds[idx] = Sg[b * (NPOS * NPOS * CC) + pos * (NPOS * CC + CC) + c];
    } else if (idx < BB * IMG + MM * KK) {
        int j  = idx - BB * IMG;            // 0..51199
        int m2 = j >> 7;                    // j / 128
        int r  = j & 127;
        int k  = r >> 1;
        int s  = r & 1;
        ((float*)g_wp)[j] = w_mu[(2 * m2 + s) * KK + k];
    } else if (idx < BB * IMG + MM * KK + KK) {
        int k = idx - (BB * IMG + MM * KK);
        g_sp[k] = log1pf(expf(w_sigma[k]));
    }
}

// ---------------- Kernel 2: mu_out + diag_vals ----------------
// grid (4 ptiles, 32 b), 256 threads: k = tid&63, pgroup = tid>>6 (4), 7 p's each.
// Each block covers p in [pt*25, pt*25+25) -> only 7 image rows needed in smem.
__global__ __launch_bounds__(256) void k_mu_diag(const float* __restrict__ mu_in,
                                                 float* __restrict__ out_mu) {
    __shared__ __align__(16) float s_mu[7 * 14 * 32];   // 3136
    __shared__ __align__(16) float s_ds[7 * 14 * 32];   // 3136
    __shared__ float s_S[7 * 14];                       // per-pos channel sums
    __shared__ float s_tr[25];

    int tid = threadIdx.x;
    int pt  = blockIdx.x;
    int b   = blockIdx.y;
    int r0  = (pt * 25) / 10;            // first image row needed
    int base = b * IMG + r0 * 14 * 32;

    for (int i = tid; i < 3136; i += 256) {
        s_mu[i] = mu_in[base + i];
        s_ds[i] = g_ds[base + i];
    }
    __syncthreads();

    if (tid < 98) {
        float s = 0.f;
        #pragma unroll
        for (int c = 0; c < 32; c++) s += s_ds[tid * 32 + c];
        s_S[tid] = s;
    }
    __syncthreads();

    if (tid < 25) {
        int p  = pt * 25 + tid;
        int pr = p / 10 - r0, pc = p % 10;
        float s = 0.f;
        #pragma unroll
        for (int i = 0; i < KS; i++)
            #pragma unroll
            for (int j = 0; j < KS; j++)
                s += s_S[(pr + i) * 14 + pc + j];
        s_tr[tid] = s;
    }
    __syncthreads();

    int k  = tid & 63;
    int pg = tid >> 6;

    int prr[7], pcc[7];
    bool act[7];
    #pragma unroll
    for (int jj = 0; jj < 7; jj++) {
        int pl = pg * 7 + jj;
        act[jj] = (pl < 25);
        int plc = act[jj] ? pl : 24;
        int p = pt * 25 + plc;
        prr[jj] = p / 10 - r0;
        pcc[jj] = p % 10;
    }

    ull accM[7], accV[7];
    #pragma unroll
    for (int jj = 0; jj < 7; jj++) { accM[jj] = 0ull; accV[jj] = 0ull; }

    const ull* wp = reinterpret_cast<const ull*>(g_wp);

    #pragma unroll 1
    for (int ij = 0; ij < 25; ij++) {
        int i = ij / 5, j = ij % 5;
        int posl[7];
        #pragma unroll
        for (int jj = 0; jj < 7; jj++)
            posl[jj] = ((prr[jj] + i) * 14 + pcc[jj] + j) * 32;
        const ull* wrow = wp + ij * 16 * 64 + k;
        #pragma unroll
        for (int c2 = 0; c2 < 16; c2++) {
            ull w2 = __ldg(wrow + c2 * 64);
            ull ws = f2mul(w2, w2);
            #pragma unroll
            for (int jj = 0; jj < 7; jj++) {
                ull a  = *reinterpret_cast<const ull*>(s_mu + posl[jj] + c2 * 2);
                ull d2 = *reinterpret_cast<const ull*>(s_ds + posl[jj] + c2 * 2);
                accM[jj] = f2fma(a,  w2, accM[jj]);
                accV[jj] = f2fma(d2, ws, accV[jj]);
            }
        }
    }

    float spk = g_sp[k];
    #pragma unroll
    for (int jj = 0; jj < 7; jj++) {
        if (act[jj]) {
            int pl = pg * 7 + jj;
            int p  = pt * 25 + pl;
            float muv = f2sum(accM[jj]);
            float v1  = f2sum(accV[jj]);
            out_mu[(b * PP + p) * KK + k] = muv;
            g_dv[(b * PP + p) * KK + k]  = v1 + spk * s_tr[pl];
        }
    }
}

// ---------------- Kernel 3: Gram G = mu_p @ mu_p^T ----------------
// grid (2 qt, 2 pt, 32 b), 128 threads (8 q-thr x 16 p-thr), thread tile 4p x 8q.
#define PADP 201
__global__ __launch_bounds__(128) void k_gram(const float* __restrict__ mu_in) {
    __shared__ __align__(16) float2 s_img[16 * PADP];  // channel-pair-major image

    int tid = threadIdx.x;
    int b   = blockIdx.z;
    const float* mb = mu_in + b * IMG;

    for (int t = tid; t < 16 * NPOS; t += 128) {
        int c2 = t & 15, pos = t >> 4;
        s_img[c2 * PADP + pos] = *reinterpret_cast<const float2*>(mb + pos * 32 + c2 * 2);
    }
    __syncthreads();

    int q0 = blockIdx.x * 64;
    int p0 = blockIdx.y * 64;
    int tx = tid & 7;    // q group
    int ty = tid >> 3;   // p group (0..15)

    int prr[4], pcc[4], qrr[8], qcc[8];
    #pragma unroll
    for (int ip = 0; ip < 4; ip++) {
        int p = p0 + ty * 4 + ip; if (p > 99) p = 99;
        prr[ip] = p / 10; pcc[ip] = p % 10;
    }
    #pragma unroll
    for (int iq = 0; iq < 8; iq++) {
        int q = q0 + tx * 8 + iq; if (q > 99) q = 99;
        qrr[iq] = q / 10; qcc[iq] = q % 10;
    }

    ull acc[4][8];
    #pragma unroll
    for (int ip = 0; ip < 4; ip++)
        #pragma unroll
        for (int iq = 0; iq < 8; iq++) acc[ip][iq] = 0ull;

    #pragma unroll 1
    for (int i = 0; i < KS; i++) {
        #pragma unroll 1
        for (int j = 0; j < KS; j++) {
            int pp[4], qq[8];
            #pragma unroll
            for (int ip = 0; ip < 4; ip++) pp[ip] = (prr[ip] + i) * 14 + pcc[ip] + j;
            #pragma unroll
            for (int iq = 0; iq < 8; iq++) qq[iq] = (qrr[iq] + i) * 14 + qcc[iq] + j;
            #pragma unroll
            for (int c2 = 0; c2 < 16; c2++) {
                const float2* basep = s_img + c2 * PADP;
                ull a[4], bq[8];
                #pragma unroll
                for (int ip = 0; ip < 4; ip++)
                    a[ip] = *reinterpret_cast<const ull*>(basep + pp[ip]);
                #pragma unroll
                for (int iq = 0; iq < 8; iq++)
                    bq[iq] = *reinterpret_cast<const ull*>(basep + qq[iq]);
                #pragma unroll
                for (int ip = 0; ip < 4; ip++)
                    #pragma unroll
                    for (int iq = 0; iq < 8; iq++)
                        acc[ip][iq] = f2fma(a[ip], bq[iq], acc[ip][iq]);
            }
        }
    }

    #pragma unroll
    for (int ip = 0; ip < 4; ip++) {
        int p = p0 + ty * 4 + ip;
        if (p < PP) {
            #pragma unroll
            for (int iq = 0; iq < 8; iq++) {
                int q = q0 + tx * 8 + iq;
                if (q < PP)
                    g_G[b * (PP * PP) + p * PP + q] = f2sum(acc[ip][iq]);
            }
        }
    }
}

// ---------------- Kernel 4: expand Sigma_out (pure bandwidth) ----------------
// grid (100 p, 32 b), 256 threads. Writes 25.6KB/block coalesced as float4.
__global__ __launch_bounds__(256) void k_expand(float* __restrict__ out) {
    __shared__ float  s_g[PP];
    __shared__ float4 s_sp[16];
    __shared__ float4 s_dv[16];

    int tid = threadIdx.x;
    int p = blockIdx.x, b = blockIdx.y;
    int bp = b * PP + p;

    if (tid < PP) s_g[tid] = g_G[b * (PP * PP) + p * PP + tid];
    if (tid >= 128 && tid < 144)
        s_sp[tid - 128] = *reinterpret_cast<const float4*>(g_sp + (tid - 128) * 4);
    if (tid >= 160 && tid < 176)
        s_dv[tid - 160] = *reinterpret_cast<const float4*>(g_dv + bp * KK + (tid - 160) * 4);
    __syncthreads();

    float* orow = out + BB * PP * KK + bp * (PP * KK);   // Sigma_out region

    #pragma unroll
    for (int it = 0; it < 7; it++) {
        int v = tid + it * 256;
        if (v < PP * 16) {
            int q = v >> 4, kc = v & 15, k4 = kc * 4;
            float g = s_g[q];
            float4 sp = s_sp[kc];
            float4 r;
            r.x = sp.x * g; r.y = sp.y * g; r.z = sp.z * g; r.w = sp.w * g;
            if (q == p) {
                float4 dv = s_dv[kc];
                r.x += dv.x; r.y += dv.y; r.z += dv.z; r.w += dv.w;
            }
            r.x = isfinite(r.x) ? r.x : 0.f;
            r.y = isfinite(r.y) ? r.y : 0.f;
            r.z = isfinite(r.z) ? r.z : 0.f;
            r.w = isfinite(r.w) ? r.w : 0.f;
            if (q == k4)     r.x = fabsf(r.x);
            if (q == k4 + 1) r.y = fabsf(r.y);
            if (q == k4 + 2) r.z = fabsf(r.z);
            if (q == k4 + 3) r.w = fabsf(r.w);
            *reinterpret_cast<float4*>(orow + 4 * v) = r;
        }
    }
}

// ---------------- launch ----------------
extern "C" void kernel_launch(void* const* d_in, const int* in_sizes, int n_in,
                              void* d_out, int out_size) {
    const float* mu_in    = (const float*)d_in[0];
    const float* Sigma_in = (const float*)d_in[1];
    const float* w_mu     = (const float*)d_in[2];
    const float* w_sigma  = (const float*)d_in[3];
    float* out = (float*)d_out;

    int prep_elems = BB * IMG + MM * KK + KK;           // 251968
    k_prep<<<(prep_elems + 255) / 256, 256>>>(Sigma_in, w_mu, w_sigma);
    k_mu_diag<<<dim3(4, BB), 256>>>(mu_in, out);
    k_gram<<<dim3(2, 2, BB), 128>>>(mu_in);
    k_expand<<<dim3(PP, BB), 256>>>(out);
}

// round 2
// speedup vs baseline: 1.3083x; 1.3083x over previous
#include <cuda_runtime.h>
#include <cuda_bf16.h>
#include <math.h>

// Problem constants
#define BB   32
#define HH   14
#define WW   14
#define CC   32
#define KK   64
#define KS   5
#define OH   10
#define OW   10
#define PP   100      // OH*OW
#define NPOS 196      // H*W
#define MM   800      // KS*KS*C
#define IMG  6272     // NPOS*CC floats per batch

// Scratch (device globals; no allocation allowed)
__device__ float  g_ds[BB * IMG];          // diag(Sigma_in) image, [b][pos][c]
__device__ float2 g_wp[(MM/2) * KK];       // paired weights: {w[2m2][k], w[2m2+1][k]} at [m2*64+k]
__device__ float  g_sp[KK];                // softplus(w_sigma)
__device__ float  g_dv[BB * PP * KK];      // diag_vals
__device__ float  g_G[BB * PP * PP];       // Gram matrices

// ---------------- f32x2 packed helpers ----------------
typedef unsigned long long ull;

__device__ __forceinline__ ull f2fma(ull a, ull b, ull c) {
    ull d;
    asm("fma.rn.f32x2 %0, %1, %2, %3;" : "=l"(d) : "l"(a), "l"(b), "l"(c));
    return d;
}
__device__ __forceinline__ ull f2mul(ull a, ull b) {
    ull d;
    asm("mul.rn.f32x2 %0, %1, %2;" : "=l"(d) : "l"(a), "l"(b));
    return d;
}
__device__ __forceinline__ float f2sum(ull v) {
    float lo, hi;
    asm("mov.b64 {%0, %1}, %2;" : "=f"(lo), "=f"(hi) : "l"(v));
    return lo + hi;
}

// ---------------- Kernel 1: prep ----------------
__global__ __launch_bounds__(256) void k_prep(const float* __restrict__ Sg,
                                              const float* __restrict__ w_mu,
                                              const float* __restrict__ w_sigma) {
    int idx = blockIdx.x * 256 + threadIdx.x;
    if (idx < BB * IMG) {
        int b   = idx / IMG;
        int r   = idx - b * IMG;
        int pos = r >> 5;
        int c   = r & 31;
        g_ds[idx] = Sg[b * (NPOS * NPOS * CC) + pos * (NPOS * CC + CC) + c];
    } else if (idx < BB * IMG + MM * KK) {
        int j  = idx - BB * IMG;
        int m2 = j >> 7;
        int r  = j & 127;
        int k  = r >> 1;
        int s  = r & 1;
        ((float*)g_wp)[j] = w_mu[(2 * m2 + s) * KK + k];
    } else if (idx < BB * IMG + MM * KK + KK) {
        int k = idx - (BB * IMG + MM * KK);
        g_sp[k] = log1pf(expf(w_sigma[k]));
    }
}

// ---------------- Kernel 2: mu_out + diag_vals ----------------
__global__ __launch_bounds__(256) void k_mu_diag(const float* __restrict__ mu_in,
                                                 float* __restrict__ out_mu) {
    __shared__ __align__(16) float s_mu[7 * 14 * 32];
    __shared__ __align__(16) float s_ds[7 * 14 * 32];
    __shared__ float s_S[7 * 14];
    __shared__ float s_tr[25];

    int tid = threadIdx.x;
    int pt  = blockIdx.x;
    int b   = blockIdx.y;
    int r0  = (pt * 25) / 10;
    int base = b * IMG + r0 * 14 * 32;

    for (int i = tid; i < 3136; i += 256) {
        s_mu[i] = mu_in[base + i];
        s_ds[i] = g_ds[base + i];
    }
    __syncthreads();

    if (tid < 98) {
        float s = 0.f;
        #pragma unroll
        for (int c = 0; c < 32; c++) s += s_ds[tid * 32 + c];
        s_S[tid] = s;
    }
    __syncthreads();

    if (tid < 25) {
        int p  = pt * 25 + tid;
        int pr = p / 10 - r0, pc = p % 10;
        float s = 0.f;
        #pragma unroll
        for (int i = 0; i < KS; i++)
            #pragma unroll
            for (int j = 0; j < KS; j++)
                s += s_S[(pr + i) * 14 + pc + j];
        s_tr[tid] = s;
    }
    __syncthreads();

    int k  = tid & 63;
    int pg = tid >> 6;

    int prr[7], pcc[7];
    bool act[7];
    #pragma unroll
    for (int jj = 0; jj < 7; jj++) {
        int pl = pg * 7 + jj;
        act[jj] = (pl < 25);
        int plc = act[jj] ? pl : 24;
        int p = pt * 25 + plc;
        prr[jj] = p / 10 - r0;
        pcc[jj] = p % 10;
    }

    ull accM[7], accV[7];
    #pragma unroll
    for (int jj = 0; jj < 7; jj++) { accM[jj] = 0ull; accV[jj] = 0ull; }

    const ull* wp = reinterpret_cast<const ull*>(g_wp);

    #pragma unroll 1
    for (int ij = 0; ij < 25; ij++) {
        int i = ij / 5, j = ij % 5;
        int posl[7];
        #pragma unroll
        for (int jj = 0; jj < 7; jj++)
            posl[jj] = ((prr[jj] + i) * 14 + pcc[jj] + j) * 32;
        const ull* wrow = wp + ij * 16 * 64 + k;
        #pragma unroll
        for (int c2 = 0; c2 < 16; c2++) {
            ull w2 = __ldg(wrow + c2 * 64);
            ull ws = f2mul(w2, w2);
            #pragma unroll
            for (int jj = 0; jj < 7; jj++) {
                ull a  = *reinterpret_cast<const ull*>(s_mu + posl[jj] + c2 * 2);
                ull d2 = *reinterpret_cast<const ull*>(s_ds + posl[jj] + c2 * 2);
                accM[jj] = f2fma(a,  w2, accM[jj]);
                accV[jj] = f2fma(d2, ws, accV[jj]);
            }
        }
    }

    float spk = g_sp[k];
    #pragma unroll
    for (int jj = 0; jj < 7; jj++) {
        if (act[jj]) {
            int pl = pg * 7 + jj;
            int p  = pt * 25 + pl;
            float muv = f2sum(accM[jj]);
            float v1  = f2sum(accV[jj]);
            out_mu[(b * PP + p) * KK + k] = muv;
            g_dv[(b * PP + p) * KK + k]  = v1 + spk * s_tr[pl];
        }
    }
}

// ---------------- Kernel 3: Gram via position-Gram factorization ----------------
// G[p,q] = sum_{d in 25 shifts} S[p_pos+d, q_pos+d],  S = X X^T over [196,32] image.
// One block per batch. S (196x198 floats, 155KB) lives in dynamic smem.
#define SROW 198
#define YPAD 198
__global__ __launch_bounds__(256) void k_gram2(const float* __restrict__ mu_in) {
    extern __shared__ float sm[];
    float*  s_S  = sm;                                    // [196][SROW]
    float2* s_yc = (float2*)(sm + NPOS * SROW);           // [16 c2][YPAD pos]

    int tid = threadIdx.x;
    int b   = blockIdx.x;
    const float* mb = mu_in + b * IMG;

    // load image in channel-pair-major layout
    for (int t = tid; t < 16 * NPOS; t += 256) {
        int c2 = t & 15, pos = t >> 4;
        s_yc[c2 * YPAD + pos] = *reinterpret_cast<const float2*>(mb + pos * 32 + c2 * 2);
    }
    __syncthreads();

    // ---- Phase 1: S = X X^T ----
    int lane = tid & 31, wg = tid >> 5;
    #pragma unroll 1
    for (int jp = 0; jp < 4; jp++) {
        int y0 = 64 * jp + 2 * lane;            // even
        bool act = (y0 < NPOS);
        int yc = act ? y0 : 0;

        ull yc0[16], yc1[16];
        #pragma unroll
        for (int c2 = 0; c2 < 16; c2++) {
            ulonglong2 v = *reinterpret_cast<const ulonglong2*>(s_yc + c2 * YPAD + yc);
            yc0[c2] = v.x;
            yc1[c2] = v.y;
        }

        #pragma unroll 1
        for (int ix = 0; ix < 25; ix++) {
            int x = wg + 8 * ix;                // uniform across warp
            if (x >= NPOS) break;
            ull acc0 = 0ull, acc1 = 0ull;
            #pragma unroll
            for (int c2 = 0; c2 < 16; c2++) {
                ull w = *reinterpret_cast<const ull*>(s_yc + c2 * YPAD + x);  // broadcast
                acc0 = f2fma(w, yc0[c2], acc0);
                acc1 = f2fma(w, yc1[c2], acc1);
            }
            if (act) {
                float2 r;
                r.x = f2sum(acc0);
                r.y = f2sum(acc1);
                *reinterpret_cast<float2*>(s_S + x * SROW + y0) = r;
            }
        }
    }
    __syncthreads();

    // ---- Phase 2: G[p,q] = sum over 25 diagonal shifts of S ----
    #pragma unroll 1
    for (int idx = tid; idx < PP * PP; idx += 256) {
        int p = idx / PP, q = idx - p * PP;
        int pr = p / 10, pc = p - pr * 10;
        int qr = q / 10, qc = q - qr * 10;
        int base = (pr * 14 + pc) * SROW + (qr * 14 + qc);
        float s = 0.f;
        #pragma unroll
        for (int i = 0; i < KS; i++)
            #pragma unroll
            for (int j = 0; j < KS; j++)
                s += s_S[base + (i * 14 + j) * (SROW + 1)];
        g_G[b * (PP * PP) + idx] = s;
    }
}

// ---------------- Kernel 4: expand Sigma_out (pure bandwidth) ----------------
__global__ __launch_bounds__(256) void k_expand(float* __restrict__ out) {
    __shared__ float  s_g[PP];
    __shared__ float4 s_sp[16];
    __shared__ float4 s_dv[16];

    int tid = threadIdx.x;
    int p = blockIdx.x, b = blockIdx.y;
    int bp = b * PP + p;

    if (tid < PP) s_g[tid] = g_G[b * (PP * PP) + p * PP + tid];
    if (tid >= 128 && tid < 144)
        s_sp[tid - 128] = *reinterpret_cast<const float4*>(g_sp + (tid - 128) * 4);
    if (tid >= 160 && tid < 176)
        s_dv[tid - 160] = *reinterpret_cast<const float4*>(g_dv + bp * KK + (tid - 160) * 4);
    __syncthreads();

    float* orow = out + BB * PP * KK + bp * (PP * KK);

    #pragma unroll
    for (int it = 0; it < 7; it++) {
        int v = tid + it * 256;
        if (v < PP * 16) {
            int q = v >> 4, kc = v & 15, k4 = kc * 4;
            float g = s_g[q];
            float4 sp = s_sp[kc];
            float4 r;
            r.x = sp.x * g; r.y = sp.y * g; r.z = sp.z * g; r.w = sp.w * g;
            if (q == p) {
                float4 dv = s_dv[kc];
                r.x += dv.x; r.y += dv.y; r.z += dv.z; r.w += dv.w;
            }
            r.x = isfinite(r.x) ? r.x : 0.f;
            r.y = isfinite(r.y) ? r.y : 0.f;
            r.z = isfinite(r.z) ? r.z : 0.f;
            r.w = isfinite(r.w) ? r.w : 0.f;
            if (q == k4)     r.x = fabsf(r.x);
            if (q == k4 + 1) r.y = fabsf(r.y);
            if (q == k4 + 2) r.z = fabsf(r.z);
            if (q == k4 + 3) r.w = fabsf(r.w);
            *reinterpret_cast<float4*>(orow + 4 * v) = r;
        }
    }
}

// ---------------- launch ----------------
extern "C" void kernel_launch(void* const* d_in, const int* in_sizes, int n_in,
                              void* d_out, int out_size) {
    const float* mu_in    = (const float*)d_in[0];
    const float* Sigma_in = (const float*)d_in[1];
    const float* w_mu     = (const float*)d_in[2];
    const float* w_sigma  = (const float*)d_in[3];
    float* out = (float*)d_out;

    const int GRAM_SMEM = NPOS * SROW * 4 + 16 * YPAD * 8;   // 155232 + 25344 = 180576
    cudaFuncSetAttribute(k_gram2, cudaFuncAttributeMaxDynamicSharedMemorySize, GRAM_SMEM);

    int prep_elems = BB * IMG + MM * KK + KK;
    k_prep<<<(prep_elems + 255) / 256, 256>>>(Sigma_in, w_mu, w_sigma);
    k_mu_diag<<<dim3(4, BB), 256>>>(mu_in, out);
    k_gram2<<<BB, 256, GRAM_SMEM>>>(mu_in);
    k_expand<<<dim3(PP, BB), 256>>>(out);
}